// round 13
// baseline (speedup 1.0000x reference)
#include <cuda_runtime.h>
#include <cuda_bf16.h>
#include <cuda_fp16.h>

// Fixed problem shapes
#define HH 512
#define WW 640
#define RAD 4             // K=9 -> R=4

// Census tile config: 16x16 threads, 8 pixels per thread -> 128x16 pixel tile
#define BXT 16
#define BYT 16
#define PX  8
#define TILE_W (BXT*PX)         // 128
#define TW (TILE_W + 2*RAD)     // 136 halves per halo row
#define TH (BYT + RAD)          // 20 halo rows (dh >= 0 only)
#define NTHREADS (BXT*BYT)      // 256

__device__ double g_acc;

// ---------------------------------------------------------------------------
// Kernel 1: pattern_proj (fp32). One block per (row, batch); 160 threads,
// strided scalar coalesced accesses (proj base is only 4B-aligned: out+lead).
// Also zeroes the global accumulator.
// ---------------------------------------------------------------------------
#define PT (WW/4)   // 160 threads
__global__ __launch_bounds__(PT)
void proj_kernel(const float* __restrict__ disp,
                 const float* __restrict__ pattern,
                 float* __restrict__ proj)
{
    int v = blockIdx.x;
    int b = blockIdx.y;
    if (v == 0 && b == 0 && threadIdx.x == 0) g_acc = 0.0;

    size_t base = ((size_t)b * HH + v) * WW;
    const float* prow = pattern + v * WW;

#pragma unroll
    for (int k = 0; k < 4; k++) {
        int u = threadIdx.x + k * PT;            // coalesced 128B/warp
        float d = disp[base + u];
        float x = (float)u - d;
        x = fminf(fmaxf(x, 0.0f), (float)(WW - 1));
        float xf = floorf(x);
        float w  = x - xf;
        int i0 = (int)xf;
        int i1 = min(i0 + 1, WW - 1);
        float g0 = __ldg(prow + i0);
        float g1 = __ldg(prow + i1);
        proj[base + u] = fmaf(w, g1 - g0, g0);
    }
}

// ---------------------------------------------------------------------------
// half2 census pair: two pixel-pairs packed in one half2 lane.
//   |ca - cb| = |da*sb - db*sa| / (sa*sb),  sa = eps+|da|, sb = eps+|db|
// Border masking via 32-bit AND on num (ALU pipe).
// ---------------------------------------------------------------------------
__device__ __forceinline__ __half2 u2h(unsigned int u) {
    return *reinterpret_cast<__half2*>(&u);
}
__device__ __forceinline__ unsigned int h2u(__half2 h) {
    return *reinterpret_cast<unsigned int*>(&h);
}

template<bool CM>
__device__ __forceinline__ void census_pair_h(unsigned int na_u, unsigned int nb_u,
                                              __half2 ac, __half2 bc,
                                              unsigned int andm, __half2& acc)
{
    const __half2 eps2 = __float2half2_rn(0.5f);
    __half2 na  = u2h(na_u);
    __half2 nb  = u2h(nb_u);
    __half2 da  = __hsub2(na, ac);
    __half2 dbn = __hsub2(bc, nb);                 // -(nb - bc)
    __half2 sa  = __hadd2(eps2, __habs2(da));
    __half2 sb  = __hadd2(eps2, __habs2(dbn));     // |dbn| == |db|
    __half2 qn  = __hmul2(dbn, sa);                // -db*sa
    __half2 num = __habs2(__hfma2(da, sb, qn));    // |da*sb - db*sa|
    __half2 den = __hmul2(sa, sb);
    __half2 r   = h2rcp(den);
    if (CM) num = u2h(h2u(num) & andm);
    acc = __hfma2(num, r, acc);
}

// Process one dh row: offsets dw = JLO-4 .. 4 for pixel pair-groups g=0..3
// (pixels 2g,2g+1). Even-parity half2s straight from 2x LDS.128 per image;
// odd-parity via PRMT. Row accumulators folded to fp32 per row.
template<int JLO, bool CM>
__device__ __forceinline__ void row_accum_h(
    const __half* __restrict__ As_row, const __half* __restrict__ Bs_row,
    int cb,
    const __half2 (&ac)[4], const __half2 (&bc)[4],
    const unsigned int (&vm)[9],
    float2 (&af)[4])
{
    const uint4* pa = (const uint4*)(As_row + cb);  // 16B aligned (cb = 8*tx halves)
    const uint4* pb = (const uint4*)(Bs_row + cb);

    unsigned int EA[8], EB[8], OA[7], OB[7];
    {
        uint4 a0 = pa[0], a1 = pa[1];
        EA[0]=a0.x; EA[1]=a0.y; EA[2]=a0.z; EA[3]=a0.w;
        EA[4]=a1.x; EA[5]=a1.y; EA[6]=a1.z; EA[7]=a1.w;
        uint4 b0 = pb[0], b1 = pb[1];
        EB[0]=b0.x; EB[1]=b0.y; EB[2]=b0.z; EB[3]=b0.w;
        EB[4]=b1.x; EB[5]=b1.y; EB[6]=b1.z; EB[7]=b1.w;
    }
#pragma unroll
    for (int k = 0; k < 7; k++) {
        OA[k] = __byte_perm(EA[k], EA[k+1], 0x5432);
        OB[k] = __byte_perm(EB[k], EB[k+1], 0x5432);
    }

    __half2 acc[4];
#pragma unroll
    for (int g = 0; g < 4; g++) acc[g] = __float2half2_rn(0.f);

#pragma unroll
    for (int j = JLO; j < 9; j++) {
#pragma unroll
        for (int g = 0; g < 4; g++) {
            const int s = j + 2*g;
            unsigned int na = (s & 1) ? OA[(s-1) >> 1] : EA[s >> 1];
            unsigned int nb = (s & 1) ? OB[(s-1) >> 1] : EB[s >> 1];
            unsigned int andm = 0xFFFFFFFFu;
            if (CM) {
                unsigned int idx = (vm[j] >> (2*g)) & 3u;
                andm = ((idx & 1u) ? 0x0000FFFFu : 0u) | ((idx & 2u) ? 0xFFFF0000u : 0u);
            }
            census_pair_h<CM>(na, nb, ac[g], bc[g], andm, acc[g]);
        }
    }

#pragma unroll
    for (int g = 0; g < 4; g++) {
        af[g].x += __low2float(acc[g]);
        af[g].y += __high2float(acc[g]);
    }
}

template<bool CM, bool FULLH>
__device__ __forceinline__ float census_block_h(
    const __half (&As)[TH][TW], const __half (&Bs)[TH][TW],
    int gx, int gy, int ty, int cb)
{
    __half2 ac[4], bc[4];
#pragma unroll
    for (int g = 0; g < 4; g++) {
        ac[g] = *(const __half2*)&As[ty][cb + RAD + 2*g];
        bc[g] = *(const __half2*)&Bs[ty][cb + RAD + 2*g];
    }

    unsigned int vm[9];
    if (CM) {
#pragma unroll
        for (int j = 0; j < 9; j++) {
            unsigned int bits = 0;
#pragma unroll
            for (int px = 0; px < PX; px++)
                if ((unsigned)(gx + px + j - 4) < WW) bits |= 1u << px;
            vm[j] = bits;
        }
    }

    float2 af[4];
#pragma unroll
    for (int g = 0; g < 4; g++) af[g] = make_float2(0.f, 0.f);

    // dh = 0 (same row), dw = 1..4  => j = 5..8
    row_accum_h<5, CM>(As[ty], Bs[ty], cb, ac, bc, vm, af);

    if (FULLH) {
#pragma unroll
        for (int dh = 1; dh <= RAD; dh++)
            row_accum_h<0, CM>(As[ty+dh], Bs[ty+dh], cb, ac, bc, vm, af);
    } else {
        int dhmax = HH - 1 - gy; if (dhmax > RAD) dhmax = RAD;
#pragma unroll 1
        for (int dh = 1; dh <= dhmax; dh++)
            row_accum_h<0, CM>(As[ty+dh], Bs[ty+dh], cb, ac, bc, vm, af);
    }
    return ((af[0].x + af[0].y) + (af[1].x + af[1].y))
         + ((af[2].x + af[2].y) + (af[3].x + af[3].y));
}

// ---------------------------------------------------------------------------
// Kernel 2: census-SAD over half-space offsets (dh>0, or dh==0 && dw>0);
// each unordered pair counted once, doubled in finalize. fp16 core.
// ---------------------------------------------------------------------------
__global__ __launch_bounds__(NTHREADS)
void census_kernel(const float* __restrict__ a_g,   // pattern_proj
                   const float* __restrict__ b_g)   // im
{
    __shared__ __align__(16) __half As[TH][TW];
    __shared__ __align__(16) __half Bs[TH][TW];

    int x0 = blockIdx.x * TILE_W;
    int y0 = blockIdx.y * BYT;
    const float* ap = a_g + (size_t)blockIdx.z * (HH * WW);
    const float* bp = b_g + (size_t)blockIdx.z * (HH * WW);
    int tid = threadIdx.y * BXT + threadIdx.x;

    for (int i = tid; i < TH * TW; i += NTHREADS) {
        int r = i / TW, c = i - r * TW;
        int gy = y0 + r;
        int gx = x0 + c - RAD;
        float av = 0.f, bv = 0.f;
        if (gy < HH && (unsigned)gx < WW) {
            int g = gy * WW + gx;
            av = ap[g];
            bv = bp[g];
        }
        As[r][c] = __float2half_rn(av);
        Bs[r][c] = __float2half_rn(bv);
    }
    __syncthreads();

    int tx = threadIdx.x, ty = threadIdx.y;
    int cb = PX * tx;            // halo col base (8*tx halves -> 16B-aligned)
    int gx = x0 + cb;
    int gy = y0 + ty;

    bool cm = (blockIdx.x == 0) || (blockIdx.x == gridDim.x - 1);
    bool fullh = (blockIdx.y != gridDim.y - 1);

    float acc;
    if (fullh) {
        acc = cm ? census_block_h<true , true >(As, Bs, gx, gy, ty, cb)
                 : census_block_h<false, true >(As, Bs, gx, gy, ty, cb);
    } else {
        acc = cm ? census_block_h<true , false>(As, Bs, gx, gy, ty, cb)
                 : census_block_h<false, false>(As, Bs, gx, gy, ty, cb);
    }

    // Block reduce. Stage 1: full-warp shfl (all 32 lanes participate).
#pragma unroll
    for (int o = 16; o > 0; o >>= 1)
        acc += __shfl_down_sync(0xffffffffu, acc, o);

    __shared__ float warpsum[NTHREADS / 32];
    if ((tid & 31) == 0) warpsum[tid >> 5] = acc;
    __syncthreads();

    // Stage 2: warp 0 only, ALL 32 lanes execute every shfl (legal masks).
    if (tid < 32) {
        float s = (tid < (NTHREADS / 32)) ? warpsum[tid] : 0.f;
#pragma unroll
        for (int o = 16; o > 0; o >>= 1)
            s += __shfl_down_sync(0xffffffffu, s, o);
        if (tid == 0) atomicAdd(&g_acc, (double)s);
    }
}

// ---------------------------------------------------------------------------
// Kernel 3: val = 2 * g_acc / (81 * B*H*W)
// ---------------------------------------------------------------------------
__global__ void finalize_kernel(float* __restrict__ out, int lead, double inv_norm)
{
    float v = (float)(2.0 * g_acc * inv_norm);
    for (int i = threadIdx.x; i < lead; i += 32) out[i] = v;
}

extern "C" void kernel_launch(void* const* d_in, const int* in_sizes, int n_in,
                              void* d_out, int out_size)
{
    const float* disp    = (const float*)d_in[0];
    const float* im      = (const float*)d_in[1];
    const float* pattern = (const float*)d_in[2];
    float* out = (float*)d_out;

    int total = in_sizes[0];           // B*1*H*W
    int B = total / (HH * WW);
    int lead = out_size - total;       // scalar(s) precede pattern_proj
    float* proj = out + lead;

    dim3 pgrid(HH, B);
    proj_kernel<<<pgrid, PT>>>(disp, pattern, proj);

    dim3 grid(WW / TILE_W, HH / BYT, B);   // 5 x 32 x B
    dim3 blk(BXT, BYT);
    census_kernel<<<grid, blk>>>(proj, im);

    finalize_kernel<<<1, 32>>>(out, lead, 1.0 / (81.0 * (double)total));
}

// round 14
// speedup vs baseline: 1.0832x; 1.0832x over previous
#include <cuda_runtime.h>
#include <cuda_bf16.h>
#include <cuda_fp16.h>

// Fixed problem shapes
#define HH 512
#define WW 640
#define RAD 4             // K=9 -> R=4

// Census tile: 32x8 threads, 4 px wide x 2 center-rows per thread -> 128x16 tile
#define BXT 32
#define BYT 8
#define PX  4
#define CROWS 2
#define TILE_W (BXT*PX)          // 128
#define TILE_H (BYT*CROWS)       // 16
#define TW (TILE_W + 2*RAD)      // 136 halves per halo row
#define TH (TILE_H + RAD)        // 20 halo rows (dh >= 0 only)
#define NTHREADS (BXT*BYT)       // 256

__device__ double g_acc;

// ---------------------------------------------------------------------------
// Kernel 1: pattern_proj (fp32, proven 17.7us). One block per (row, batch);
// 160 threads, strided scalar coalesced accesses (proj base only 4B-aligned).
// Also zeroes the global accumulator.
// ---------------------------------------------------------------------------
#define PT (WW/4)   // 160 threads
__global__ __launch_bounds__(PT)
void proj_kernel(const float* __restrict__ disp,
                 const float* __restrict__ pattern,
                 float* __restrict__ proj)
{
    int v = blockIdx.x;
    int b = blockIdx.y;
    if (v == 0 && b == 0 && threadIdx.x == 0) g_acc = 0.0;

    size_t base = ((size_t)b * HH + v) * WW;
    const float* prow = pattern + v * WW;

#pragma unroll
    for (int k = 0; k < 4; k++) {
        int u = threadIdx.x + k * PT;            // coalesced 128B/warp
        float d = disp[base + u];
        float x = (float)u - d;
        x = fminf(fmaxf(x, 0.0f), (float)(WW - 1));
        float xf = floorf(x);
        float w  = x - xf;
        int i0 = (int)xf;
        int i1 = min(i0 + 1, WW - 1);
        float g0 = __ldg(prow + i0);
        float g1 = __ldg(prow + i1);
        proj[base + u] = fmaf(w, g1 - g0, g0);
    }
}

// ---------------------------------------------------------------------------
// half2 census pair (as R13, verified): |ca-cb| = |da*sb - db*sa|/(sa*sb)
// with border masking via 32-bit AND on num.
// ---------------------------------------------------------------------------
__device__ __forceinline__ __half2 u2h(unsigned int u) {
    return *reinterpret_cast<__half2*>(&u);
}
__device__ __forceinline__ unsigned int h2u(__half2 h) {
    return *reinterpret_cast<unsigned int*>(&h);
}

template<bool CM>
__device__ __forceinline__ void census_pair_h(unsigned int na_u, unsigned int nb_u,
                                              __half2 ac, __half2 bc,
                                              unsigned int andm, __half2& acc)
{
    const __half2 eps2 = __float2half2_rn(0.5f);
    __half2 na  = u2h(na_u);
    __half2 nb  = u2h(nb_u);
    __half2 da  = __hsub2(na, ac);
    __half2 dbn = __hsub2(bc, nb);                 // -(nb - bc)
    __half2 sa  = __hadd2(eps2, __habs2(da));
    __half2 sb  = __hadd2(eps2, __habs2(dbn));     // |dbn| == |db|
    __half2 qn  = __hmul2(dbn, sa);                // -db*sa
    __half2 num = __habs2(__hfma2(da, sb, qn));    // |da*sb - db*sa|
    __half2 den = __hmul2(sa, sb);
    __half2 r   = h2rcp(den);
    if (CM) num = u2h(h2u(num) & andm);
    acc = __hfma2(num, r, acc);
}

// ---------------------------------------------------------------------------
// Shared-row op: one smem row feeds TWO center rows (c0 at dh=r, c1 at dh=r-1).
// JLOc = first j (offset dw = j-4) used by center c; JLOc = 9 disables center c.
// Operands loaded ONCE (6 LDS.64 + PRMT odd-parity), reused by up to 4 chains.
// Per-row half2 accs folded into shared fp32 accumulators (all sums commute).
// ---------------------------------------------------------------------------
template<int JLO0, int JLO1, bool CM>
__device__ __forceinline__ void row_shared(
    const __half* __restrict__ As_row, const __half* __restrict__ Bs_row,
    int cb,
    const __half2 (&ac0)[2], const __half2 (&bc0)[2],
    const __half2 (&ac1)[2], const __half2 (&bc1)[2],
    const unsigned int (&vm)[9], float2 (&af)[2])
{
    constexpr int JMIN = (JLO0 < JLO1) ? JLO0 : JLO1;
    const uint2* pa = (const uint2*)(As_row + cb);   // 8B aligned
    const uint2* pb = (const uint2*)(Bs_row + cb);

    unsigned int EA[6], EB[6], OA[5], OB[5];
    constexpr int F2_LO = (JMIN >= 5) ? 1 : 0;
    constexpr int OK_LO = (JMIN >= 5) ? 2 : 0;
#pragma unroll
    for (int f = F2_LO; f < 3; f++) {
        uint2 va = pa[f]; EA[2*f] = va.x; EA[2*f+1] = va.y;
        uint2 vb = pb[f]; EB[2*f] = vb.x; EB[2*f+1] = vb.y;
    }
#pragma unroll
    for (int k = OK_LO; k < 5; k++) {
        OA[k] = __byte_perm(EA[k], EA[k+1], 0x5432);
        OB[k] = __byte_perm(EB[k], EB[k+1], 0x5432);
    }

    __half2 a00 = __float2half2_rn(0.f), a01 = a00, a10 = a00, a11 = a00;

#pragma unroll
    for (int j = JMIN; j < 9; j++) {
        const int s0 = j;        // group 0: pixels 0,1
        const int s1 = j + 2;    // group 1: pixels 2,3
        unsigned int na0 = (s0 & 1) ? OA[(s0-1) >> 1] : EA[s0 >> 1];
        unsigned int nb0 = (s0 & 1) ? OB[(s0-1) >> 1] : EB[s0 >> 1];
        unsigned int na1 = (s1 & 1) ? OA[(s1-1) >> 1] : EA[s1 >> 1];
        unsigned int nb1 = (s1 & 1) ? OB[(s1-1) >> 1] : EB[s1 >> 1];
        unsigned int m0 = 0xFFFFFFFFu, m1 = 0xFFFFFFFFu;
        if (CM) {
            unsigned int bits = vm[j];
            m0 = ((bits & 1u) ? 0x0000FFFFu : 0u) | ((bits & 2u) ? 0xFFFF0000u : 0u);
            m1 = ((bits & 4u) ? 0x0000FFFFu : 0u) | ((bits & 8u) ? 0xFFFF0000u : 0u);
        }
        if (j >= JLO0) {
            census_pair_h<CM>(na0, nb0, ac0[0], bc0[0], m0, a00);
            census_pair_h<CM>(na1, nb1, ac0[1], bc0[1], m1, a01);
        }
        if (j >= JLO1) {
            census_pair_h<CM>(na0, nb0, ac1[0], bc1[0], m0, a10);
            census_pair_h<CM>(na1, nb1, ac1[1], bc1[1], m1, a11);
        }
    }

    if (JLO0 < 9) {
        af[0].x += __low2float(a00); af[0].y += __high2float(a00);
        af[1].x += __low2float(a01); af[1].y += __high2float(a01);
    }
    if (JLO1 < 9) {
        af[0].x += __low2float(a10); af[0].y += __high2float(a10);
        af[1].x += __low2float(a11); af[1].y += __high2float(a11);
    }
}

// ---------------------------------------------------------------------------
// Per-thread census over 4 px x 2 adjacent center rows (r0 = 2*ty, r0+1).
// Half-space offsets (dh>0, or dh==0 && dw>0); doubled in finalize.
// ---------------------------------------------------------------------------
template<bool CM, bool FULLH>
__device__ __forceinline__ float census_block2(
    const __half (&As)[TH][TW], const __half (&Bs)[TH][TW],
    int gx, int gy0, int r0, int cb)
{
    __half2 ac0[2], bc0[2], ac1[2], bc1[2];
#pragma unroll
    for (int g = 0; g < 2; g++) {
        ac0[g] = *(const __half2*)&As[r0  ][cb + RAD + 2*g];
        bc0[g] = *(const __half2*)&Bs[r0  ][cb + RAD + 2*g];
        ac1[g] = *(const __half2*)&As[r0+1][cb + RAD + 2*g];
        bc1[g] = *(const __half2*)&Bs[r0+1][cb + RAD + 2*g];
    }

    unsigned int vm[9];
    if (CM) {
#pragma unroll
        for (int j = 0; j < 9; j++) {
            unsigned int bits = 0;
#pragma unroll
            for (int px = 0; px < PX; px++)
                if ((unsigned)(gx + px + j - 4) < WW) bits |= 1u << px;
            vm[j] = bits;
        }
    }

    float2 af[2];
    af[0] = make_float2(0.f, 0.f);
    af[1] = make_float2(0.f, 0.f);

    if (FULLH) {
        // row r0+rr serves c0 at dh=rr (JLO 5 if dh==0 else 0)
        //                  c1 at dh=rr-1 (JLO 5 if dh==0 else 0; none for rr==0)
        row_shared<5, 9, CM>(As[r0  ], Bs[r0  ], cb, ac0, bc0, ac1, bc1, vm, af);
        row_shared<0, 5, CM>(As[r0+1], Bs[r0+1], cb, ac0, bc0, ac1, bc1, vm, af);
        row_shared<0, 0, CM>(As[r0+2], Bs[r0+2], cb, ac0, bc0, ac1, bc1, vm, af);
        row_shared<0, 0, CM>(As[r0+3], Bs[r0+3], cb, ac0, bc0, ac1, bc1, vm, af);
        row_shared<0, 0, CM>(As[r0+4], Bs[r0+4], cb, ac0, bc0, ac1, bc1, vm, af);
        row_shared<9, 0, CM>(As[r0+5], Bs[r0+5], cb, ac0, bc0, ac1, bc1, vm, af);
    } else {
        // bottom tile: per-center dynamic row count (center1 slot disabled)
        row_shared<5, 9, CM>(As[r0], Bs[r0], cb, ac0, bc0, ac0, bc0, vm, af);
        int dm0 = HH - 1 - gy0; if (dm0 > RAD) dm0 = RAD;
#pragma unroll 1
        for (int dh = 1; dh <= dm0; dh++)
            row_shared<0, 9, CM>(As[r0+dh], Bs[r0+dh], cb, ac0, bc0, ac0, bc0, vm, af);

        row_shared<5, 9, CM>(As[r0+1], Bs[r0+1], cb, ac1, bc1, ac1, bc1, vm, af);
        int dm1 = HH - 2 - gy0; if (dm1 > RAD) dm1 = RAD;
#pragma unroll 1
        for (int dh = 1; dh <= dm1; dh++)
            row_shared<0, 9, CM>(As[r0+1+dh], Bs[r0+1+dh], cb, ac1, bc1, ac1, bc1, vm, af);
    }
    return (af[0].x + af[0].y) + (af[1].x + af[1].y);
}

__global__ __launch_bounds__(NTHREADS)
void census_kernel(const float* __restrict__ a_g,   // pattern_proj
                   const float* __restrict__ b_g)   // im
{
    __shared__ __align__(16) __half As[TH][TW];
    __shared__ __align__(16) __half Bs[TH][TW];

    int x0 = blockIdx.x * TILE_W;
    int y0 = blockIdx.y * TILE_H;
    const float* ap = a_g + (size_t)blockIdx.z * (HH * WW);
    const float* bp = b_g + (size_t)blockIdx.z * (HH * WW);
    int tid = threadIdx.y * BXT + threadIdx.x;

    for (int i = tid; i < TH * TW; i += NTHREADS) {
        int r = i / TW, c = i - r * TW;
        int gy = y0 + r;
        int gx = x0 + c - RAD;
        float av = 0.f, bv = 0.f;
        if (gy < HH && (unsigned)gx < WW) {
            int g = gy * WW + gx;
            av = ap[g];
            bv = bp[g];
        }
        As[r][c] = __float2half_rn(av);
        Bs[r][c] = __float2half_rn(bv);
    }
    __syncthreads();

    int tx = threadIdx.x, ty = threadIdx.y;
    int cb = PX * tx;            // halo col base (4*tx halves -> 8B-aligned)
    int gx = x0 + cb;
    int r0 = CROWS * ty;         // first of this thread's 2 center rows
    int gy0 = y0 + r0;

    bool cm = (blockIdx.x == 0) || (blockIdx.x == gridDim.x - 1);
    bool fullh = (blockIdx.y != gridDim.y - 1);

    float acc;
    if (fullh) {
        acc = cm ? census_block2<true , true >(As, Bs, gx, gy0, r0, cb)
                 : census_block2<false, true >(As, Bs, gx, gy0, r0, cb);
    } else {
        acc = cm ? census_block2<true , false>(As, Bs, gx, gy0, r0, cb)
                 : census_block2<false, false>(As, Bs, gx, gy0, r0, cb);
    }

    // Block reduce. Stage 1: full-warp shfl (all 32 lanes participate).
#pragma unroll
    for (int o = 16; o > 0; o >>= 1)
        acc += __shfl_down_sync(0xffffffffu, acc, o);

    __shared__ float warpsum[NTHREADS / 32];
    if ((tid & 31) == 0) warpsum[tid >> 5] = acc;
    __syncthreads();

    // Stage 2: warp 0 only, ALL 32 lanes execute every shfl (legal masks).
    if (tid < 32) {
        float s = (tid < (NTHREADS / 32)) ? warpsum[tid] : 0.f;
#pragma unroll
        for (int o = 16; o > 0; o >>= 1)
            s += __shfl_down_sync(0xffffffffu, s, o);
        if (tid == 0) atomicAdd(&g_acc, (double)s);
    }
}

// ---------------------------------------------------------------------------
// Kernel 3: val = 2 * g_acc / (81 * B*H*W)
// ---------------------------------------------------------------------------
__global__ void finalize_kernel(float* __restrict__ out, int lead, double inv_norm)
{
    float v = (float)(2.0 * g_acc * inv_norm);
    for (int i = threadIdx.x; i < lead; i += 32) out[i] = v;
}

extern "C" void kernel_launch(void* const* d_in, const int* in_sizes, int n_in,
                              void* d_out, int out_size)
{
    const float* disp    = (const float*)d_in[0];
    const float* im      = (const float*)d_in[1];
    const float* pattern = (const float*)d_in[2];
    float* out = (float*)d_out;

    int total = in_sizes[0];           // B*1*H*W
    int B = total / (HH * WW);
    int lead = out_size - total;       // scalar(s) precede pattern_proj
    float* proj = out + lead;

    dim3 pgrid(HH, B);
    proj_kernel<<<pgrid, PT>>>(disp, pattern, proj);

    dim3 grid(WW / TILE_W, HH / TILE_H, B);   // 5 x 32 x B
    dim3 blk(BXT, BYT);
    census_kernel<<<grid, blk>>>(proj, im);

    finalize_kernel<<<1, 32>>>(out, lead, 1.0 / (81.0 * (double)total));
}